// round 4
// baseline (speedup 1.0000x reference)
#include <cuda_runtime.h>
#include <cuda_bf16.h>

#define N_PTS 65536
#define D     256
#define D4    64
#define K     2048

#define BP 128   // points per block tile
#define BC 256   // codes per block tile
#define DB 32    // d-chunk

// ---------------- scratch (no allocs allowed) ----------------
__device__ int   g_ind[N_PTS];
__device__ float g_xnorm[N_PTS];
__device__ float g_enorm[K];
__device__ float g_counts[K];
__device__ float g_esum[K * D];
__device__ float g_total;

// ---------------- f32x2 helpers (FFMA2) ----------------
static __device__ __forceinline__ unsigned long long fma2(unsigned long long a,
                                                          unsigned long long b,
                                                          unsigned long long c) {
    unsigned long long d;
    asm("fma.rn.f32x2 %0, %1, %2, %3;" : "=l"(d) : "l"(a), "l"(b), "l"(c));
    return d;
}
static __device__ __forceinline__ unsigned long long dup2(float x) {
    unsigned long long r;
    asm("mov.b64 %0, {%1, %2};" : "=l"(r) : "f"(x), "f"(x));
    return r;
}
static __device__ __forceinline__ float2 unpk(unsigned long long v) {
    float2 f;
    asm("mov.b64 {%0, %1}, %2;" : "=f"(f.x), "=f"(f.y) : "l"(v));
    return f;
}

// ---------------- kernel 1: row norms of x and embed ----------------
__global__ void norm_kernel(const float* __restrict__ x, const float* __restrict__ embed) {
    int warp = (blockIdx.x * blockDim.x + threadIdx.x) >> 5;
    int lane = threadIdx.x & 31;
    if (warp >= N_PTS + K) return;
    const float* src = (warp < N_PTS) ? (x + (size_t)warp * D)
                                      : (embed + (size_t)(warp - N_PTS) * D);
    float s = 0.f;
    for (int i = lane; i < D; i += 32) { float v = src[i]; s = fmaf(v, v, s); }
    #pragma unroll
    for (int o = 16; o > 0; o >>= 1) s += __shfl_down_sync(0xffffffffu, s, o);
    if (lane == 0) {
        if (warp < N_PTS) g_xnorm[warp] = s;
        else              g_enorm[warp - N_PTS] = s;
    }
}

// ---------------- kernel 2: fused distance GEMM + argmin ----------------
// block: 256 threads = 16(tx: codes) x 16(ty: points)
// micro-tile per thread: 8 points x 16 codes (codes packed as 8 f32x2)
__global__ __launch_bounds__(256, 1)
void argmin_kernel(const float* __restrict__ x, const float* __restrict__ embed,
                   float* __restrict__ out_ind) {
    extern __shared__ float sm[];
    float* xs   = sm;                       // [DB][BP]  transposed x chunk
    float* es   = sm + DB * BP;             // [DB][BC]  transposed e chunk
    float* s_en = sm + DB * BP + DB * BC;   // [K] code norms

    const int tid = threadIdx.x;
    const int tx  = tid & 15;
    const int ty  = tid >> 4;
    const int n0  = blockIdx.x * BP;

    const float4* x4 = (const float4*)x;
    const float4* e4 = (const float4*)embed;

    for (int i = tid; i < K; i += 256) s_en[i] = g_enorm[i];

    float xn[8];
    #pragma unroll
    for (int p = 0; p < 8; p++) xn[p] = g_xnorm[n0 + ty * 8 + p];

    float bv[8]; int bi[8];
    #pragma unroll
    for (int p = 0; p < 8; p++) { bv[p] = 3.4e38f; bi[p] = 0; }

    unsigned long long acc[8][8];

    for (int kt = 0; kt < K / BC; kt++) {
        #pragma unroll
        for (int p = 0; p < 8; p++)
            #pragma unroll
            for (int j = 0; j < 8; j++) acc[p][j] = 0ull;

        const int c0 = kt * BC;
        for (int dc = 0; dc < D / DB; dc++) {
            const int dq = dc * (DB / 4);  // float4 offset along d
            __syncthreads();
            // load x chunk (1024 float4, coalesced), store transposed [d][p]
            #pragma unroll
            for (int r = 0; r < 4; r++) {
                int f = r * 256 + tid;
                int p = f >> 3, jj = f & 7;
                float4 v = x4[(size_t)(n0 + p) * D4 + dq + jj];
                xs[(jj * 4 + 0) * BP + p] = v.x;
                xs[(jj * 4 + 1) * BP + p] = v.y;
                xs[(jj * 4 + 2) * BP + p] = v.z;
                xs[(jj * 4 + 3) * BP + p] = v.w;
            }
            // load e chunk (2048 float4, coalesced), store transposed [d][c]
            #pragma unroll
            for (int r = 0; r < 8; r++) {
                int f = r * 256 + tid;
                int c = f >> 3, jj = f & 7;
                float4 v = e4[(size_t)(c0 + c) * D4 + dq + jj];
                es[(jj * 4 + 0) * BC + c] = v.x;
                es[(jj * 4 + 1) * BC + c] = v.y;
                es[(jj * 4 + 2) * BC + c] = v.z;
                es[(jj * 4 + 3) * BC + c] = v.w;
            }
            __syncthreads();

            #pragma unroll 8
            for (int dd = 0; dd < DB; dd++) {
                const float* xrow = xs + dd * BP + ty * 8;
                float4 xa = *(const float4*)(xrow);
                float4 xb = *(const float4*)(xrow + 4);
                unsigned long long xd[8];
                xd[0] = dup2(xa.x); xd[1] = dup2(xa.y);
                xd[2] = dup2(xa.z); xd[3] = dup2(xa.w);
                xd[4] = dup2(xb.x); xd[5] = dup2(xb.y);
                xd[6] = dup2(xb.z); xd[7] = dup2(xb.w);
                unsigned long long e2[8];
                const float* erow = es + dd * BC;
                #pragma unroll
                for (int g = 0; g < 4; g++) {
                    ulonglong2 ev = *(const ulonglong2*)(erow + g * 64 + tx * 4);
                    e2[g * 2]     = ev.x;
                    e2[g * 2 + 1] = ev.y;
                }
                #pragma unroll
                for (int p = 0; p < 8; p++)
                    #pragma unroll
                    for (int j = 0; j < 8; j++)
                        acc[p][j] = fma2(xd[p], e2[j], acc[p][j]);
            }
        }

        // epilogue for this code tile: dist = (||x||^2 - 2*dot) + ||e||^2
        #pragma unroll
        for (int p = 0; p < 8; p++) {
            #pragma unroll
            for (int j = 0; j < 8; j++) {   // ascending code index for this thread
                int g = j >> 1, h = j & 1;
                int c = c0 + g * 64 + tx * 4 + h * 2;
                float2 dp = unpk(acc[p][j]);
                float s0 = __fmaf_rn(-2.f, dp.x, xn[p]) + s_en[c];
                float s1 = __fmaf_rn(-2.f, dp.y, xn[p]) + s_en[c + 1];
                if (s0 < bv[p]) { bv[p] = s0; bi[p] = c; }
                if (s1 < bv[p]) { bv[p] = s1; bi[p] = c + 1; }
            }
        }
    }

    // cross-thread (tx) reduction per point; tie -> smallest code index
    __syncthreads();
    float* rv = es;                 // alias: [16][BP]
    int*   ri = (int*)(es + 16 * BP);
    #pragma unroll
    for (int p = 0; p < 8; p++) {
        rv[tx * BP + ty * 8 + p] = bv[p];
        ri[tx * BP + ty * 8 + p] = bi[p];
    }
    __syncthreads();
    if (tid < BP) {
        float best = rv[tid]; int bidx = ri[tid];
        #pragma unroll
        for (int t = 1; t < 16; t++) {
            float v = rv[t * BP + tid]; int i = ri[t * BP + tid];
            if (v < best || (v == best && i < bidx)) { best = v; bidx = i; }
        }
        int n = n0 + tid;
        g_ind[n]   = bidx;
        out_ind[n] = (float)bidx;
        atomicAdd(&g_counts[bidx], 1.0f);   // exact integer-valued adds
    }
}

// ---------------- kernel 3: quantize gather + per-code feature sums ----------------
__global__ void gather_kernel(const float* __restrict__ x, const float* __restrict__ embed,
                              float* __restrict__ out_q) {
    int t = blockIdx.x * blockDim.x + threadIdx.x;  // N*64 threads (float4 granularity)
    int n = t >> 6, q = t & 63;
    int idx = g_ind[n];
    float4 ev = ((const float4*)embed)[(size_t)idx * D4 + q];
    ((float4*)out_q)[(size_t)n * D4 + q] = ev;
    float4 xv = ((const float4*)x)[(size_t)n * D4 + q];
    float* es = g_esum + (size_t)idx * D + q * 4;
    atomicAdd(es + 0, xv.x);
    atomicAdd(es + 1, xv.y);
    atomicAdd(es + 2, xv.z);
    atomicAdd(es + 3, xv.w);
}

// ---------------- kernel 4: new_cluster_size + total ----------------
__global__ void ncs_kernel(const float* __restrict__ cs, float* __restrict__ out_ncs) {
    __shared__ float red[1024];
    int tid = threadIdx.x;
    float s = 0.f;
    for (int k = tid; k < K; k += 1024) {
        float v = cs[k] * 0.99f + 0.01f * g_counts[k];
        out_ncs[k] = v;
        s += v;
    }
    red[tid] = s;
    __syncthreads();
    for (int o = 512; o > 0; o >>= 1) {
        if (tid < o) red[tid] += red[tid + o];
        __syncthreads();
    }
    if (tid == 0) g_total = red[0];
}

// ---------------- kernel 5: new_embed_avg + new_embed ----------------
__global__ void fin_kernel(const float* __restrict__ cs, const float* __restrict__ ea,
                           float* __restrict__ out_nea, float* __restrict__ out_ne) {
    int j = blockIdx.x * blockDim.x + threadIdx.x;  // K*D
    int k = j >> 8;
    float nea = ea[j] * 0.99f + 0.01f * g_esum[j];
    out_nea[j] = nea;
    float ncs = cs[k] * 0.99f + 0.01f * g_counts[k];
    float tot = g_total;
    float smv = (ncs + 1e-6f) / (tot + 0.002048f) * tot;   // laplace smoothing, EPS*K = 0.002048
    out_ne[j] = nea / smv;
}

// ---------------- launch ----------------
extern "C" void kernel_launch(void* const* d_in, const int* in_sizes, int n_in,
                              void* d_out, int out_size) {
    const float* x  = (const float*)d_in[0];
    const float* em = (const float*)d_in[1];
    const float* cs = (const float*)d_in[2];
    const float* ea = (const float*)d_in[3];
    float* out      = (float*)d_out;

    float* out_q   = out;                               // [N, D]
    float* out_ind = out + (size_t)N_PTS * D;           // [N]
    float* out_ncs = out_ind + N_PTS;                   // [K]
    float* out_nea = out_ncs + K;                       // [K, D]
    float* out_ne  = out_nea + (size_t)K * D;           // [K, D]

    void* p_esum; cudaGetSymbolAddress(&p_esum, g_esum);
    void* p_cnt;  cudaGetSymbolAddress(&p_cnt,  g_counts);
    cudaMemsetAsync(p_esum, 0, sizeof(float) * K * D, 0);
    cudaMemsetAsync(p_cnt,  0, sizeof(float) * K, 0);

    norm_kernel<<<(N_PTS + K) / 8, 256>>>(x, em);

    int smem = (DB * BP + DB * BC + K) * (int)sizeof(float);  // 57344 bytes
    cudaFuncSetAttribute(argmin_kernel, cudaFuncAttributeMaxDynamicSharedMemorySize, smem);
    argmin_kernel<<<N_PTS / BP, 256, smem>>>(x, em, out_ind);

    gather_kernel<<<(N_PTS * 64) / 256, 256>>>(x, em, out_q);
    ncs_kernel<<<1, 1024>>>(cs, out_ncs);
    fin_kernel<<<(K * D) / 256, 256>>>(cs, ea, out_nea, out_ne);
}

// round 6
// speedup vs baseline: 1.0440x; 1.0440x over previous
#include <cuda_runtime.h>
#include <cuda_bf16.h>

#define N_PTS 65536
#define D     256
#define D4    64
#define K     2048

#define BP 128   // points per block tile
#define BC 256   // codes per block tile
#define DB 32    // d-chunk

// ---------------- scratch (no allocs allowed) ----------------
__device__ int   g_ind[N_PTS];
__device__ float g_xnorm[N_PTS];
__device__ float g_enorm[K];
__device__ float g_counts[K];
__device__ float g_esum[K * D];
__device__ float g_total;

// ---------------- f32x2 helpers (FFMA2) ----------------
static __device__ __forceinline__ unsigned long long fma2(unsigned long long a,
                                                          unsigned long long b,
                                                          unsigned long long c) {
    unsigned long long d;
    asm("fma.rn.f32x2 %0, %1, %2, %3;" : "=l"(d) : "l"(a), "l"(b), "l"(c));
    return d;
}
static __device__ __forceinline__ unsigned long long dup2(float x) {
    unsigned long long r;
    asm("mov.b64 %0, {%1, %2};" : "=l"(r) : "f"(x), "f"(x));
    return r;
}
static __device__ __forceinline__ float2 unpk(unsigned long long v) {
    float2 f;
    asm("mov.b64 {%0, %1}, %2;" : "=f"(f.x), "=f"(f.y) : "l"(v));
    return f;
}

// ---------------- kernel 1: row norms of x and embed ----------------
__global__ void norm_kernel(const float* __restrict__ x, const float* __restrict__ embed) {
    int warp = (blockIdx.x * blockDim.x + threadIdx.x) >> 5;
    int lane = threadIdx.x & 31;
    if (warp >= N_PTS + K) return;
    const float* src = (warp < N_PTS) ? (x + (size_t)warp * D)
                                      : (embed + (size_t)(warp - N_PTS) * D);
    float s = 0.f;
    for (int i = lane; i < D; i += 32) { float v = src[i]; s = fmaf(v, v, s); }
    #pragma unroll
    for (int o = 16; o > 0; o >>= 1) s += __shfl_down_sync(0xffffffffu, s, o);
    if (lane == 0) {
        if (warp < N_PTS) g_xnorm[warp] = s;
        else              g_enorm[warp - N_PTS] = s;
    }
}

// ---------------- kernel 2: fused distance GEMM + argmin ----------------
// block: 256 threads = 16(tx: codes) x 16(ty: points)
// micro-tile per thread: 8 points x 16 codes (codes packed as 8 f32x2)
__global__ __launch_bounds__(256, 1)
void argmin_kernel(const float* __restrict__ x, const float* __restrict__ embed,
                   float* __restrict__ out_ind) {
    extern __shared__ float sm[];
    float* xs   = sm;                       // [DB][BP]  transposed x chunk
    float* es   = sm + DB * BP;             // [DB][BC]  transposed e chunk
    float* s_en = sm + DB * BP + DB * BC;   // [K] code norms

    const int tid = threadIdx.x;
    const int tx  = tid & 15;
    const int ty  = tid >> 4;
    const int n0  = blockIdx.x * BP;

    const float4* x4 = (const float4*)x;
    const float4* e4 = (const float4*)embed;

    for (int i = tid; i < K; i += 256) s_en[i] = g_enorm[i];

    float xn[8];
    #pragma unroll
    for (int p = 0; p < 8; p++) xn[p] = g_xnorm[n0 + ty * 8 + p];

    float bv[8]; int bi[8];
    #pragma unroll
    for (int p = 0; p < 8; p++) { bv[p] = 3.4e38f; bi[p] = 0; }

    unsigned long long acc[8][8];

    for (int kt = 0; kt < K / BC; kt++) {
        #pragma unroll
        for (int p = 0; p < 8; p++)
            #pragma unroll
            for (int j = 0; j < 8; j++) acc[p][j] = 0ull;

        const int c0 = kt * BC;
        for (int dc = 0; dc < D / DB; dc++) {
            const int dq = dc * (DB / 4);  // float4 offset along d
            __syncthreads();
            // load x chunk (1024 float4, coalesced), store transposed [d][p]
            #pragma unroll
            for (int r = 0; r < 4; r++) {
                int f = r * 256 + tid;
                int p = f >> 3, jj = f & 7;
                float4 v = x4[(size_t)(n0 + p) * D4 + dq + jj];
                xs[(jj * 4 + 0) * BP + p] = v.x;
                xs[(jj * 4 + 1) * BP + p] = v.y;
                xs[(jj * 4 + 2) * BP + p] = v.z;
                xs[(jj * 4 + 3) * BP + p] = v.w;
            }
            // load e chunk (2048 float4, coalesced), store transposed [d][c]
            #pragma unroll
            for (int r = 0; r < 8; r++) {
                int f = r * 256 + tid;
                int c = f >> 3, jj = f & 7;
                float4 v = e4[(size_t)(c0 + c) * D4 + dq + jj];
                es[(jj * 4 + 0) * BC + c] = v.x;
                es[(jj * 4 + 1) * BC + c] = v.y;
                es[(jj * 4 + 2) * BC + c] = v.z;
                es[(jj * 4 + 3) * BC + c] = v.w;
            }
            __syncthreads();

            #pragma unroll 8
            for (int dd = 0; dd < DB; dd++) {
                const float* xrow = xs + dd * BP + ty * 8;
                float4 xa = *(const float4*)(xrow);
                float4 xb = *(const float4*)(xrow + 4);
                unsigned long long xd[8];
                xd[0] = dup2(xa.x); xd[1] = dup2(xa.y);
                xd[2] = dup2(xa.z); xd[3] = dup2(xa.w);
                xd[4] = dup2(xb.x); xd[5] = dup2(xb.y);
                xd[6] = dup2(xb.z); xd[7] = dup2(xb.w);
                unsigned long long e2[8];
                const float* erow = es + dd * BC;
                #pragma unroll
                for (int g = 0; g < 4; g++) {
                    ulonglong2 ev = *(const ulonglong2*)(erow + g * 64 + tx * 4);
                    e2[g * 2]     = ev.x;
                    e2[g * 2 + 1] = ev.y;
                }
                #pragma unroll
                for (int p = 0; p < 8; p++)
                    #pragma unroll
                    for (int j = 0; j < 8; j++)
                        acc[p][j] = fma2(xd[p], e2[j], acc[p][j]);
            }
        }

        // epilogue for this code tile: dist = (||x||^2 - 2*dot) + ||e||^2
        #pragma unroll
        for (int p = 0; p < 8; p++) {
            #pragma unroll
            for (int j = 0; j < 8; j++) {   // ascending code index for this thread
                int g = j >> 1, h = j & 1;
                int c = c0 + g * 64 + tx * 4 + h * 2;
                float2 dp = unpk(acc[p][j]);
                float s0 = __fmaf_rn(-2.f, dp.x, xn[p]) + s_en[c];
                float s1 = __fmaf_rn(-2.f, dp.y, xn[p]) + s_en[c + 1];
                if (s0 < bv[p]) { bv[p] = s0; bi[p] = c; }
                if (s1 < bv[p]) { bv[p] = s1; bi[p] = c + 1; }
            }
        }
    }

    // cross-thread (tx) reduction per point; tie -> smallest code index
    __syncthreads();
    float* rv = es;                 // alias: [16][BP]
    int*   ri = (int*)(es + 16 * BP);
    #pragma unroll
    for (int p = 0; p < 8; p++) {
        rv[tx * BP + ty * 8 + p] = bv[p];
        ri[tx * BP + ty * 8 + p] = bi[p];
    }
    __syncthreads();
    if (tid < BP) {
        float best = rv[tid]; int bidx = ri[tid];
        #pragma unroll
        for (int t = 1; t < 16; t++) {
            float v = rv[t * BP + tid]; int i = ri[t * BP + tid];
            if (v < best || (v == best && i < bidx)) { best = v; bidx = i; }
        }
        int n = n0 + tid;
        g_ind[n]   = bidx;
        out_ind[n] = (float)bidx;
        atomicAdd(&g_counts[bidx], 1.0f);   // exact integer-valued adds
    }
}

// ---------------- kernel 3: quantize gather + per-code feature sums ----------------
__global__ void gather_kernel(const float* __restrict__ x, const float* __restrict__ embed,
                              float* __restrict__ out_q) {
    int t = blockIdx.x * blockDim.x + threadIdx.x;  // N*64 threads (float4 granularity)
    int n = t >> 6, q = t & 63;
    int idx = g_ind[n];
    float4 ev = ((const float4*)embed)[(size_t)idx * D4 + q];
    ((float4*)out_q)[(size_t)n * D4 + q] = ev;
    float4 xv = ((const float4*)x)[(size_t)n * D4 + q];
    float* es = g_esum + (size_t)idx * D + q * 4;
    atomicAdd(es + 0, xv.x);
    atomicAdd(es + 1, xv.y);
    atomicAdd(es + 2, xv.z);
    atomicAdd(es + 3, xv.w);
}

// ---------------- kernel 4: new_cluster_size + total ----------------
__global__ void ncs_kernel(const float* __restrict__ cs, float* __restrict__ out_ncs) {
    __shared__ float red[1024];
    int tid = threadIdx.x;
    float s = 0.f;
    for (int k = tid; k < K; k += 1024) {
        float v = cs[k] * 0.99f + 0.01f * g_counts[k];
        out_ncs[k] = v;
        s += v;
    }
    red[tid] = s;
    __syncthreads();
    for (int o = 512; o > 0; o >>= 1) {
        if (tid < o) red[tid] += red[tid + o];
        __syncthreads();
    }
    if (tid == 0) g_total = red[0];
}

// ---------------- kernel 5: new_embed_avg + new_embed ----------------
__global__ void fin_kernel(const float* __restrict__ cs, const float* __restrict__ ea,
                           float* __restrict__ out_nea, float* __restrict__ out_ne) {
    int j = blockIdx.x * blockDim.x + threadIdx.x;  // K*D
    int k = j >> 8;
    float nea = ea[j] * 0.99f + 0.01f * g_esum[j];
    out_nea[j] = nea;
    float ncs = cs[k] * 0.99f + 0.01f * g_counts[k];
    float tot = g_total;
    float smv = (ncs + 1e-6f) / (tot + 0.002048f) * tot;   // laplace smoothing, EPS*K = 0.002048
    out_ne[j] = nea / smv;
}

// ---------------- launch ----------------
extern "C" void kernel_launch(void* const* d_in, const int* in_sizes, int n_in,
                              void* d_out, int out_size) {
    const float* x  = (const float*)d_in[0];
    const float* em = (const float*)d_in[1];
    const float* cs = (const float*)d_in[2];
    const float* ea = (const float*)d_in[3];
    float* out      = (float*)d_out;

    float* out_q   = out;                               // [N, D]
    float* out_ind = out + (size_t)N_PTS * D;           // [N]
    float* out_ncs = out_ind + N_PTS;                   // [K]
    float* out_nea = out_ncs + K;                       // [K, D]
    float* out_ne  = out_nea + (size_t)K * D;           // [K, D]

    void* p_esum; cudaGetSymbolAddress(&p_esum, g_esum);
    void* p_cnt;  cudaGetSymbolAddress(&p_cnt,  g_counts);
    cudaMemsetAsync(p_esum, 0, sizeof(float) * K * D, 0);
    cudaMemsetAsync(p_cnt,  0, sizeof(float) * K, 0);

    norm_kernel<<<(N_PTS + K) / 8, 256>>>(x, em);

    int smem = (DB * BP + DB * BC + K) * (int)sizeof(float);  // 57344 bytes
    cudaFuncSetAttribute(argmin_kernel, cudaFuncAttributeMaxDynamicSharedMemorySize, smem);
    argmin_kernel<<<N_PTS / BP, 256, smem>>>(x, em, out_ind);

    gather_kernel<<<(N_PTS * 64) / 256, 256>>>(x, em, out_q);
    ncs_kernel<<<1, 1024>>>(cs, out_ncs);
    fin_kernel<<<(K * D) / 256, 256>>>(cs, ea, out_nea, out_ne);
}

// round 8
// speedup vs baseline: 2.3877x; 2.2871x over previous
#include <cuda_runtime.h>
#include <cuda_bf16.h>
#include <cstdint>

#define N_PTS 65536
#define D     256
#define D4    64
#define K     2048
#define TH    0.15f

// ---------------- scratch (no allocs allowed) ----------------
__device__ int   g_ind[N_PTS];
__device__ float g_xnorm[N_PTS];
__device__ float g_enorm[K];
__device__ float g_counts[K];
__device__ float g_esum[K * D];
__device__ float g_total;
__device__ int   g_flag[N_PTS];
__device__ int   g_nflag;
// x packed in A-fragment order: [ptile 512][mt 8][kstep 32][lane 32][4]
__device__ __align__(1024) float g_Apk[N_PTS * D];
// e packed in B-fragment order: [ct 8][kc 8][nt 32][ksl 4][lane 32][2]
__device__ __align__(1024) float g_Bpk[K * D];

// ---------------- PTX helpers ----------------
static __device__ __forceinline__ uint32_t smem_u32(const void* p) {
    uint32_t a;
    asm("{ .reg .u64 t; cvta.to.shared.u64 t, %1; cvt.u32.u64 %0, t; }" : "=r"(a) : "l"(p));
    return a;
}
static __device__ __forceinline__ uint32_t f2tf32(float f) {
    uint32_t r;
    asm("cvt.rna.tf32.f32 %0, %1;" : "=r"(r) : "f"(f));
    return r;
}
static __device__ __forceinline__ void mbar_init(uint32_t a, uint32_t cnt) {
    asm volatile("mbarrier.init.shared.b64 [%0], %1;" :: "r"(a), "r"(cnt) : "memory");
}
static __device__ __forceinline__ void mbar_expect(uint32_t a, uint32_t tx) {
    asm volatile("mbarrier.arrive.expect_tx.shared.b64 _, [%0], %1;" :: "r"(a), "r"(tx) : "memory");
}
static __device__ __forceinline__ void mbar_wait(uint32_t a, uint32_t ph) {
    asm volatile(
        "{\n\t.reg .pred P;\n"
        "LW%=:\n\t"
        "mbarrier.try_wait.parity.acquire.cta.shared::cta.b64 P, [%0], %1, 0x989680;\n\t"
        "@P bra LD%=;\n\t"
        "bra LW%=;\n"
        "LD%=:\n\t}"
        :: "r"(a), "r"(ph) : "memory");
}
static __device__ __forceinline__ void bulkcp(uint32_t dst, const void* src, uint32_t bytes, uint32_t mbar) {
    asm volatile("cp.async.bulk.shared::cta.global.mbarrier::complete_tx::bytes [%0], [%1], %2, [%3];"
                 :: "r"(dst), "l"(src), "r"(bytes), "r"(mbar) : "memory");
}
static __device__ __forceinline__ uint4 lds128(uint32_t a) {
    uint4 v;
    asm volatile("ld.shared.v4.b32 {%0,%1,%2,%3}, [%4];"
                 : "=r"(v.x), "=r"(v.y), "=r"(v.z), "=r"(v.w) : "r"(a));
    return v;
}
static __device__ __forceinline__ uint2 lds64(uint32_t a) {
    uint2 v;
    asm volatile("ld.shared.v2.b32 {%0,%1}, [%2];" : "=r"(v.x), "=r"(v.y) : "r"(a));
    return v;
}
#define MMA_TF32(C, Av, Bv) \
    asm volatile("mma.sync.aligned.m16n8k8.row.col.f32.tf32.tf32.f32 " \
                 "{%0,%1,%2,%3}, {%4,%5,%6,%7}, {%8,%9}, {%0,%1,%2,%3};" \
                 : "+f"((C)[0]), "+f"((C)[1]), "+f"((C)[2]), "+f"((C)[3]) \
                 : "r"((Av).x), "r"((Av).y), "r"((Av).z), "r"((Av).w), \
                   "r"((Bv).x), "r"((Bv).y))

// ---------------- prep: tf32 fragment packing + exact fp32 norms ----------------
// one warp per row; lane l handles dims 8l..8l+7
__global__ void prep_x_kernel(const float* __restrict__ x) {
    int w = (blockIdx.x * blockDim.x + threadIdx.x) >> 5;   // point
    int l = threadIdx.x & 31;
    const float4* x4 = (const float4*)x;
    float4 v0 = x4[(size_t)w * D4 + l * 2];
    float4 v1 = x4[(size_t)w * D4 + l * 2 + 1];
    float f[8] = {v0.x, v0.y, v0.z, v0.w, v1.x, v1.y, v1.z, v1.w};
    float s = 0.f;
    #pragma unroll
    for (int i = 0; i < 8; i++) s = fmaf(f[i], f[i], s);
    #pragma unroll
    for (int o = 16; o > 0; o >>= 1) s += __shfl_down_sync(0xffffffffu, s, o);
    if (l == 0) g_xnorm[w] = s;
    // A frag element (row = g + 8a, col = tig + 4b) -> reg q = a + 2b
    int pt = w >> 7, r = w & 127, mt = r >> 4, a = (r >> 3) & 1, g = r & 7;
    size_t base = ((size_t)(pt * 8 + mt) * 32 + l) * 32;   // kstep = l
    #pragma unroll
    for (int kk = 0; kk < 8; kk++) {
        int tig = kk & 3, bb = kk >> 2;
        g_Apk[(base + (g * 4 + tig)) * 4 + (a + 2 * bb)] = __uint_as_float(f2tf32(f[kk]));
    }
}

__global__ void prep_e_kernel(const float* __restrict__ e) {
    int w = (blockIdx.x * blockDim.x + threadIdx.x) >> 5;   // code
    int l = threadIdx.x & 31;
    const float4* e4 = (const float4*)e;
    float4 v0 = e4[(size_t)w * D4 + l * 2];
    float4 v1 = e4[(size_t)w * D4 + l * 2 + 1];
    float f[8] = {v0.x, v0.y, v0.z, v0.w, v1.x, v1.y, v1.z, v1.w};
    float s = 0.f;
    #pragma unroll
    for (int i = 0; i < 8; i++) s = fmaf(f[i], f[i], s);
    #pragma unroll
    for (int o = 16; o > 0; o >>= 1) s += __shfl_down_sync(0xffffffffu, s, o);
    if (l == 0) g_enorm[w] = s;
    // B frag element (k = tig + 4b, n = g) -> reg q = b
    int ct = w >> 8, c = w & 255, nt = c >> 3, g = c & 7;
    int kc = l >> 2, ksl = l & 3;                           // k = 8l + kk
    size_t base = ((((size_t)ct * 8 + kc) * 32 + nt) * 4 + ksl) * 32;
    #pragma unroll
    for (int kk = 0; kk < 8; kk++) {
        int tig = kk & 3, bb = kk >> 2;
        g_Bpk[(base + (g * 4 + tig)) * 2 + bb] = __uint_as_float(f2tf32(f[kk]));
    }
}

// ---------------- main: tf32 mma.sync GEMM + streaming argmin with margin ----------------
// 256 threads = 8 warps (2 M-warps x 4 N-warps), warp tile 64 pts x 64 codes
// block tile: 128 pts x 256 codes per iteration, 8 iterations cover K codes
__global__ __launch_bounds__(256, 1)
void argmin_gemm_kernel(float* __restrict__ out_ind) {
    extern __shared__ float dyn[];          // A: 131072 B, then B stages: 2 x 32768 B
    __shared__ float s_en[K];
    __shared__ float s_mv[4 * 128];
    __shared__ int   s_mi[4 * 128];
    __shared__ float s_m2[4 * 128];
    __shared__ __align__(8) unsigned long long s_bar[3];   // afull, bfull0, bfull1

    const int tid  = threadIdx.x;
    const int lane = tid & 31;
    const int warp = tid >> 5;
    const int mw   = warp >> 2;    // 0..1
    const int nw   = warp & 3;     // 0..3
    const int g    = lane >> 2;
    const int tig  = lane & 3;
    const int n0   = blockIdx.x * 128;

    const uint32_t sbA = smem_u32(dyn);
    const uint32_t sbB = sbA + 131072;
    const uint32_t mb_afull = smem_u32(&s_bar[0]);
    const uint32_t mb_bf0   = smem_u32(&s_bar[1]);
    const uint32_t mb_bf1   = smem_u32(&s_bar[2]);

    if (tid == 0) {
        mbar_init(mb_afull, 1);
        mbar_init(mb_bf0, 1);
        mbar_init(mb_bf1, 1);
    }
    for (int i = tid; i < K; i += 256) s_en[i] = g_enorm[i];
    __syncthreads();
    if (tid == 0) {
        mbar_expect(mb_afull, 131072);
        bulkcp(sbA, (const void*)&g_Apk[(size_t)blockIdx.x * 32768], 131072, mb_afull);
        mbar_expect(mb_bf0, 32768);
        bulkcp(sbB, (const void*)&g_Bpk[0], 32768, mb_bf0);
        mbar_expect(mb_bf1, 32768);
        bulkcp(sbB + 32768, (const void*)&g_Bpk[8192], 32768, mb_bf1);
    }

    float xnv[8];
    #pragma unroll
    for (int t = 0; t < 8; t++) {
        int row = mw * 64 + (t >> 1) * 16 + (t & 1) * 8 + g;
        xnv[t] = g_xnorm[n0 + row];
    }
    float m1[8], m2[8]; int i1v[8];
    #pragma unroll
    for (int t = 0; t < 8; t++) { m1[t] = 3.4e38f; m2[t] = 3.4e38f; i1v[t] = 0; }

    mbar_wait(mb_afull, 0);

    for (int iter = 0; iter < 8; iter++) {
        float acc[4][8][4];
        #pragma unroll
        for (int mt = 0; mt < 4; mt++)
            #pragma unroll
            for (int nt = 0; nt < 8; nt++)
                #pragma unroll
                for (int q = 0; q < 4; q++) acc[mt][nt][q] = 0.f;

        for (int kc = 0; kc < 8; kc++) {
            const int cidx = iter * 8 + kc;
            const int st = cidx & 1;
            const uint32_t bfu = st ? mb_bf1 : mb_bf0;
            mbar_wait(bfu, (cidx >> 1) & 1);
            #pragma unroll
            for (int ksl = 0; ksl < 4; ksl++) {
                const int kg = kc * 4 + ksl;   // global kstep 0..31
                uint4 Af[4];
                #pragma unroll
                for (int mt = 0; mt < 4; mt++)
                    Af[mt] = lds128(sbA + (uint32_t)((((mw * 4 + mt) * 32 + kg) * 32 + lane) * 16));
                uint2 Bf[8];
                #pragma unroll
                for (int nt = 0; nt < 8; nt++)
                    Bf[nt] = lds64(sbB + (uint32_t)(st * 32768 + (((nw * 8 + nt) * 4 + ksl) * 32 + lane) * 8));
                #pragma unroll
                for (int mt = 0; mt < 4; mt++)
                    #pragma unroll
                    for (int nt = 0; nt < 8; nt++)
                        MMA_TF32(acc[mt][nt], Af[mt], Bf[nt]);
            }
            __syncthreads();   // all warps done reading stage st
            if (tid == 0 && cidx + 2 < 64) {
                mbar_expect(bfu, 32768);
                bulkcp(sbB + st * 32768, (const void*)&g_Bpk[(size_t)(cidx + 2) * 8192], 32768, bfu);
            }
        }

        // epilogue: dist = (||x||^2 - 2*dot) + ||e||^2, track min1/min2
        #pragma unroll
        for (int mt = 0; mt < 4; mt++) {
            #pragma unroll
            for (int rr = 0; rr < 2; rr++) {
                const int t = mt * 2 + rr;
                const float xv = xnv[t];
                #pragma unroll
                for (int nt = 0; nt < 8; nt++) {
                    #pragma unroll
                    for (int j = 0; j < 2; j++) {
                        int code = iter * 256 + nw * 64 + nt * 8 + 2 * tig + j;
                        float dist = fmaf(-2.f, acc[mt][nt][rr * 2 + j], xv) + s_en[code];
                        if (dist < m1[t]) { m2[t] = m1[t]; m1[t] = dist; i1v[t] = code; }
                        else if (dist < m2[t]) m2[t] = dist;
                    }
                }
            }
        }
    }

    // reduce across tig (quad) via shfl; lanes in a quad share the same rows
    #pragma unroll
    for (int t = 0; t < 8; t++) {
        float a = m1[t]; int ai = i1v[t]; float b = m2[t];
        #pragma unroll
        for (int o = 1; o <= 2; o <<= 1) {
            float o1 = __shfl_xor_sync(0xffffffffu, a, o);
            int   oi = __shfl_xor_sync(0xffffffffu, ai, o);
            float o2 = __shfl_xor_sync(0xffffffffu, b, o);
            if (o1 < a || (o1 == a && oi < ai)) { b = fminf(a, o2); a = o1; ai = oi; }
            else b = fminf(b, o1);
        }
        if (tig == 0) {
            int row = mw * 64 + (t >> 1) * 16 + (t & 1) * 8 + g;
            s_mv[nw * 128 + row] = a;
            s_mi[nw * 128 + row] = ai;
            s_m2[nw * 128 + row] = b;
        }
    }
    __syncthreads();

    if (tid < 128) {
        float a = s_mv[tid]; int ai = s_mi[tid]; float b = s_m2[tid];
        #pragma unroll
        for (int w = 1; w < 4; w++) {
            float o1 = s_mv[w * 128 + tid]; int oi = s_mi[w * 128 + tid]; float o2 = s_m2[w * 128 + tid];
            if (o1 < a || (o1 == a && oi < ai)) { b = fminf(a, o2); a = o1; ai = oi; }
            else b = fminf(b, o1);
        }
        int n = n0 + tid;
        if (b - a > TH) {
            g_ind[n] = ai;
            out_ind[n] = (float)ai;
            atomicAdd(&g_counts[ai], 1.0f);   // exact integer-valued adds
        } else {
            int pos = atomicAdd(&g_nflag, 1);
            g_flag[pos] = n;
        }
    }
}

// ---------------- exact fp32 fallback for near-tie points ----------------
__global__ void fallback_kernel(const float* __restrict__ x, const float* __restrict__ embed,
                                float* __restrict__ out_ind) {
    __shared__ float xs[4 * 256];
    __shared__ float xnv[4];
    __shared__ int   pts[4];
    __shared__ float fv[4 * 256];
    __shared__ int   fi[4 * 256];
    const int tid = threadIdx.x;
    const int nf = g_nflag;
    for (int base = blockIdx.x * 4; base < nf; base += gridDim.x * 4) {
        int cnt = min(4, nf - base);
        __syncthreads();
        if (tid < 4) {
            int p = g_flag[base + ((tid < cnt) ? tid : 0)];
            pts[tid] = p;
            xnv[tid] = g_xnorm[p];
        }
        __syncthreads();
        for (int i = tid; i < 4 * 256; i += 256) xs[i] = x[(size_t)pts[i >> 8] * D + (i & 255)];
        __syncthreads();
        float best[4] = {3.4e38f, 3.4e38f, 3.4e38f, 3.4e38f};
        int bi[4] = {0, 0, 0, 0};
        const float4* xs4 = (const float4*)xs;
        for (int cc = 0; cc < 8; cc++) {
            int c = cc * 256 + tid;
            const float4* e4 = (const float4*)(embed + (size_t)c * D);
            float a0 = 0.f, a1 = 0.f, a2 = 0.f, a3 = 0.f;
            #pragma unroll 8
            for (int d = 0; d < 64; d++) {
                float4 ev = e4[d];
                float4 x0 = xs4[d], x1 = xs4[64 + d], x2 = xs4[128 + d], x3 = xs4[192 + d];
                a0 = fmaf(ev.x, x0.x, a0); a0 = fmaf(ev.y, x0.y, a0); a0 = fmaf(ev.z, x0.z, a0); a0 = fmaf(ev.w, x0.w, a0);
                a1 = fmaf(ev.x, x1.x, a1); a1 = fmaf(ev.y, x1.y, a1); a1 = fmaf(ev.z, x1.z, a1); a1 = fmaf(ev.w, x1.w, a1);
                a2 = fmaf(ev.x, x2.x, a2); a2 = fmaf(ev.y, x2.y, a2); a2 = fmaf(ev.z, x2.z, a2); a2 = fmaf(ev.w, x2.w, a2);
                a3 = fmaf(ev.x, x3.x, a3); a3 = fmaf(ev.y, x3.y, a3); a3 = fmaf(ev.z, x3.z, a3); a3 = fmaf(ev.w, x3.w, a3);
            }
            float en = g_enorm[c];
            float d0 = fmaf(-2.f, a0, xnv[0]) + en;
            float d1 = fmaf(-2.f, a1, xnv[1]) + en;
            float d2 = fmaf(-2.f, a2, xnv[2]) + en;
            float d3 = fmaf(-2.f, a3, xnv[3]) + en;
            if (d0 < best[0]) { best[0] = d0; bi[0] = c; }
            if (d1 < best[1]) { best[1] = d1; bi[1] = c; }
            if (d2 < best[2]) { best[2] = d2; bi[2] = c; }
            if (d3 < best[3]) { best[3] = d3; bi[3] = c; }
        }
        #pragma unroll
        for (int p = 0; p < 4; p++) { fv[p * 256 + tid] = best[p]; fi[p * 256 + tid] = bi[p]; }
        __syncthreads();
        if (tid < cnt) {
            float bb = fv[tid * 256]; int bidx = fi[tid * 256];
            for (int j = 1; j < 256; j++) {
                float v = fv[tid * 256 + j]; int ix = fi[tid * 256 + j];
                if (v < bb || (v == bb && ix < bidx)) { bb = v; bidx = ix; }
            }
            int n = pts[tid];
            g_ind[n] = bidx;
            out_ind[n] = (float)bidx;
            atomicAdd(&g_counts[bidx], 1.0f);
        }
    }
}

// ---------------- quantize gather + per-code feature sums ----------------
__global__ void gather_kernel(const float* __restrict__ x, const float* __restrict__ embed,
                              float* __restrict__ out_q) {
    int t = blockIdx.x * blockDim.x + threadIdx.x;
    int n = t >> 6, q = t & 63;
    int idx = g_ind[n];
    float4 ev = ((const float4*)embed)[(size_t)idx * D4 + q];
    ((float4*)out_q)[(size_t)n * D4 + q] = ev;
    float4 xv = ((const float4*)x)[(size_t)n * D4 + q];
    float* es = g_esum + (size_t)idx * D + q * 4;
    atomicAdd(es + 0, xv.x);
    atomicAdd(es + 1, xv.y);
    atomicAdd(es + 2, xv.z);
    atomicAdd(es + 3, xv.w);
}

// ---------------- new_cluster_size + total ----------------
__global__ void ncs_kernel(const float* __restrict__ cs, float* __restrict__ out_ncs) {
    __shared__ float red[1024];
    int tid = threadIdx.x;
    float s = 0.f;
    for (int k = tid; k < K; k += 1024) {
        float v = cs[k] * 0.99f + 0.01f * g_counts[k];
        out_ncs[k] = v;
        s += v;
    }
    red[tid] = s;
    __syncthreads();
    for (int o = 512; o > 0; o >>= 1) {
        if (tid < o) red[tid] += red[tid + o];
        __syncthreads();
    }
    if (tid == 0) g_total = red[0];
}

// ---------------- new_embed_avg + new_embed ----------------
__global__ void fin_kernel(const float* __restrict__ cs, const float* __restrict__ ea,
                           float* __restrict__ out_nea, float* __restrict__ out_ne) {
    int j = blockIdx.x * blockDim.x + threadIdx.x;
    int k = j >> 8;
    float nea = ea[j] * 0.99f + 0.01f * g_esum[j];
    out_nea[j] = nea;
    float ncs = cs[k] * 0.99f + 0.01f * g_counts[k];
    float tot = g_total;
    float smv = (ncs + 1e-6f) / (tot + 0.002048f) * tot;   // laplace smoothing, EPS*K
    out_ne[j] = nea / smv;
}

// ---------------- launch ----------------
extern "C" void kernel_launch(void* const* d_in, const int* in_sizes, int n_in,
                              void* d_out, int out_size) {
    const float* x  = (const float*)d_in[0];
    const float* em = (const float*)d_in[1];
    const float* cs = (const float*)d_in[2];
    const float* ea = (const float*)d_in[3];
    float* out      = (float*)d_out;

    float* out_q   = out;                               // [N, D]
    float* out_ind = out + (size_t)N_PTS * D;           // [N]
    float* out_ncs = out_ind + N_PTS;                   // [K]
    float* out_nea = out_ncs + K;                       // [K, D]
    float* out_ne  = out_nea + (size_t)K * D;           // [K, D]

    void* p_esum; cudaGetSymbolAddress(&p_esum, g_esum);
    void* p_cnt;  cudaGetSymbolAddress(&p_cnt,  g_counts);
    void* p_nfl;  cudaGetSymbolAddress(&p_nfl,  g_nflag);
    cudaMemsetAsync(p_esum, 0, sizeof(float) * K * D, 0);
    cudaMemsetAsync(p_cnt,  0, sizeof(float) * K, 0);
    cudaMemsetAsync(p_nfl,  0, sizeof(int), 0);

    prep_x_kernel<<<N_PTS / 8, 256>>>(x);
    prep_e_kernel<<<K / 8, 256>>>(em);

    cudaFuncSetAttribute(argmin_gemm_kernel, cudaFuncAttributeMaxDynamicSharedMemorySize, 196608);
    argmin_gemm_kernel<<<N_PTS / 128, 256, 196608>>>(out_ind);

    fallback_kernel<<<148, 256>>>(x, em, out_ind);
    gather_kernel<<<(N_PTS * 64) / 256, 256>>>(x, em, out_q);
    ncs_kernel<<<1, 1024>>>(cs, out_ncs);
    fin_kernel<<<(K * D) / 256, 256>>>(cs, ea, out_nea, out_ne);
}

// round 10
// speedup vs baseline: 2.6358x; 1.1039x over previous
#include <cuda_runtime.h>
#include <cuda_bf16.h>
#include <cstdint>

#define N_PTS 65536
#define D     256
#define D4    64
#define K     2048
#define TH    0.15f

// ---------------- scratch (no allocs allowed) ----------------
__device__ int   g_ind[N_PTS];
__device__ float g_xnorm[N_PTS];
__device__ float g_enorm[K];
__device__ float g_counts[K];
__device__ float g_esum[K * D];
__device__ float g_total;
__device__ int   g_flag[N_PTS];
__device__ int   g_nflag;
__device__ unsigned long long g_best[N_PTS];
// x packed in A-fragment order: [ptile 512][mt 8][kstep 32][lane 32][4]
__device__ __align__(1024) float g_Apk[N_PTS * D];
// e packed in B-fragment order: [ct 8][kc 8][nt 32][ksl 4][lane 32][2]
__device__ __align__(1024) float g_Bpk[K * D];

// ---------------- PTX helpers ----------------
static __device__ __forceinline__ uint32_t smem_u32(const void* p) {
    uint32_t a;
    asm("{ .reg .u64 t; cvta.to.shared.u64 t, %1; cvt.u32.u64 %0, t; }" : "=r"(a) : "l"(p));
    return a;
}
static __device__ __forceinline__ uint32_t f2tf32(float f) {
    uint32_t r;
    asm("cvt.rna.tf32.f32 %0, %1;" : "=r"(r) : "f"(f));
    return r;
}
static __device__ __forceinline__ void mbar_init(uint32_t a, uint32_t cnt) {
    asm volatile("mbarrier.init.shared.b64 [%0], %1;" :: "r"(a), "r"(cnt) : "memory");
}
static __device__ __forceinline__ void mbar_expect(uint32_t a, uint32_t tx) {
    asm volatile("mbarrier.arrive.expect_tx.shared.b64 _, [%0], %1;" :: "r"(a), "r"(tx) : "memory");
}
static __device__ __forceinline__ void mbar_wait(uint32_t a, uint32_t ph) {
    asm volatile(
        "{\n\t.reg .pred P;\n"
        "LW%=:\n\t"
        "mbarrier.try_wait.parity.acquire.cta.shared::cta.b64 P, [%0], %1, 0x989680;\n\t"
        "@P bra LD%=;\n\t"
        "bra LW%=;\n"
        "LD%=:\n\t}"
        :: "r"(a), "r"(ph) : "memory");
}
static __device__ __forceinline__ void bulkcp(uint32_t dst, const void* src, uint32_t bytes, uint32_t mbar) {
    asm volatile("cp.async.bulk.shared::cta.global.mbarrier::complete_tx::bytes [%0], [%1], %2, [%3];"
                 :: "r"(dst), "l"(src), "r"(bytes), "r"(mbar) : "memory");
}
static __device__ __forceinline__ uint4 lds128(uint32_t a) {
    uint4 v;
    asm volatile("ld.shared.v4.b32 {%0,%1,%2,%3}, [%4];"
                 : "=r"(v.x), "=r"(v.y), "=r"(v.z), "=r"(v.w) : "r"(a));
    return v;
}
static __device__ __forceinline__ uint2 lds64(uint32_t a) {
    uint2 v;
    asm volatile("ld.shared.v2.b32 {%0,%1}, [%2];" : "=r"(v.x), "=r"(v.y) : "r"(a));
    return v;
}
#define MMA_TF32(C, Av, Bv) \
    asm volatile("mma.sync.aligned.m16n8k8.row.col.f32.tf32.tf32.f32 " \
                 "{%0,%1,%2,%3}, {%4,%5,%6,%7}, {%8,%9}, {%0,%1,%2,%3};" \
                 : "+f"((C)[0]), "+f"((C)[1]), "+f"((C)[2]), "+f"((C)[3]) \
                 : "r"((Av).x), "r"((Av).y), "r"((Av).z), "r"((Av).w), \
                   "r"((Bv).x), "r"((Bv).y))

// ---------------- prep: tf32 fragment packing + exact fp32 norms ----------------
__global__ void prep_x_kernel(const float* __restrict__ x) {
    int w = (blockIdx.x * blockDim.x + threadIdx.x) >> 5;   // point
    int l = threadIdx.x & 31;
    const float4* x4 = (const float4*)x;
    float4 v0 = x4[(size_t)w * D4 + l * 2];
    float4 v1 = x4[(size_t)w * D4 + l * 2 + 1];
    float f[8] = {v0.x, v0.y, v0.z, v0.w, v1.x, v1.y, v1.z, v1.w};
    float s = 0.f;
    #pragma unroll
    for (int i = 0; i < 8; i++) s = fmaf(f[i], f[i], s);
    #pragma unroll
    for (int o = 16; o > 0; o >>= 1) s += __shfl_down_sync(0xffffffffu, s, o);
    if (l == 0) g_xnorm[w] = s;
    int pt = w >> 7, r = w & 127, mt = r >> 4, a = (r >> 3) & 1, g = r & 7;
    size_t base = ((size_t)(pt * 8 + mt) * 32 + l) * 32;   // kstep = l
    #pragma unroll
    for (int kk = 0; kk < 8; kk++) {
        int tig = kk & 3, bb = kk >> 2;
        g_Apk[(base + (g * 4 + tig)) * 4 + (a + 2 * bb)] = __uint_as_float(f2tf32(f[kk]));
    }
}

__global__ void prep_e_kernel(const float* __restrict__ e) {
    int w = (blockIdx.x * blockDim.x + threadIdx.x) >> 5;   // code
    int l = threadIdx.x & 31;
    const float4* e4 = (const float4*)e;
    float4 v0 = e4[(size_t)w * D4 + l * 2];
    float4 v1 = e4[(size_t)w * D4 + l * 2 + 1];
    float f[8] = {v0.x, v0.y, v0.z, v0.w, v1.x, v1.y, v1.z, v1.w};
    float s = 0.f;
    #pragma unroll
    for (int i = 0; i < 8; i++) s = fmaf(f[i], f[i], s);
    #pragma unroll
    for (int o = 16; o > 0; o >>= 1) s += __shfl_down_sync(0xffffffffu, s, o);
    if (l == 0) g_enorm[w] = s;
    int ct = w >> 8, c = w & 255, nt = c >> 3, g = c & 7;
    int kc = l >> 2, ksl = l & 3;
    size_t base = ((((size_t)ct * 8 + kc) * 32 + nt) * 4 + ksl) * 32;
    #pragma unroll
    for (int kk = 0; kk < 8; kk++) {
        int tig = kk & 3, bb = kk >> 2;
        g_Bpk[(base + (g * 4 + tig)) * 2 + bb] = __uint_as_float(f2tf32(f[kk]));
    }
}

// ---------------- main: tf32 mma.sync GEMM + streaming argmin with margin ----------------
__global__ __launch_bounds__(256, 1)
void argmin_gemm_kernel(float* __restrict__ out_ind) {
    extern __shared__ float dyn[];          // A: 131072 B, then B stages: 2 x 32768 B
    __shared__ float s_en[K];
    __shared__ float s_mv[4 * 128];
    __shared__ int   s_mi[4 * 128];
    __shared__ float s_m2[4 * 128];
    __shared__ __align__(8) unsigned long long s_bar[3];

    const int tid  = threadIdx.x;
    const int lane = tid & 31;
    const int warp = tid >> 5;
    const int mw   = warp >> 2;
    const int nw   = warp & 3;
    const int g    = lane >> 2;
    const int tig  = lane & 3;
    const int n0   = blockIdx.x * 128;

    const uint32_t sbA = smem_u32(dyn);
    const uint32_t sbB = sbA + 131072;
    const uint32_t mb_afull = smem_u32(&s_bar[0]);
    const uint32_t mb_bf0   = smem_u32(&s_bar[1]);
    const uint32_t mb_bf1   = smem_u32(&s_bar[2]);

    if (tid == 0) {
        mbar_init(mb_afull, 1);
        mbar_init(mb_bf0, 1);
        mbar_init(mb_bf1, 1);
    }
    for (int i = tid; i < K; i += 256) s_en[i] = g_enorm[i];
    __syncthreads();
    if (tid == 0) {
        mbar_expect(mb_afull, 131072);
        bulkcp(sbA, (const void*)&g_Apk[(size_t)blockIdx.x * 32768], 131072, mb_afull);
        mbar_expect(mb_bf0, 32768);
        bulkcp(sbB, (const void*)&g_Bpk[0], 32768, mb_bf0);
        mbar_expect(mb_bf1, 32768);
        bulkcp(sbB + 32768, (const void*)&g_Bpk[8192], 32768, mb_bf1);
    }

    float xnv[8];
    #pragma unroll
    for (int t = 0; t < 8; t++) {
        int row = mw * 64 + (t >> 1) * 16 + (t & 1) * 8 + g;
        xnv[t] = g_xnorm[n0 + row];
    }
    float m1[8], m2[8]; int i1v[8];
    #pragma unroll
    for (int t = 0; t < 8; t++) { m1[t] = 3.4e38f; m2[t] = 3.4e38f; i1v[t] = 0; }

    mbar_wait(mb_afull, 0);

    for (int iter = 0; iter < 8; iter++) {
        float acc[4][8][4];
        #pragma unroll
        for (int mt = 0; mt < 4; mt++)
            #pragma unroll
            for (int nt = 0; nt < 8; nt++)
                #pragma unroll
                for (int q = 0; q < 4; q++) acc[mt][nt][q] = 0.f;

        for (int kc = 0; kc < 8; kc++) {
            const int cidx = iter * 8 + kc;
            const int st = cidx & 1;
            const uint32_t bfu = st ? mb_bf1 : mb_bf0;
            mbar_wait(bfu, (cidx >> 1) & 1);
            #pragma unroll
            for (int ksl = 0; ksl < 4; ksl++) {
                const int kg = kc * 4 + ksl;
                uint4 Af[4];
                #pragma unroll
                for (int mt = 0; mt < 4; mt++)
                    Af[mt] = lds128(sbA + (uint32_t)((((mw * 4 + mt) * 32 + kg) * 32 + lane) * 16));
                uint2 Bf[8];
                #pragma unroll
                for (int nt = 0; nt < 8; nt++)
                    Bf[nt] = lds64(sbB + (uint32_t)(st * 32768 + (((nw * 8 + nt) * 4 + ksl) * 32 + lane) * 8));
                #pragma unroll
                for (int mt = 0; mt < 4; mt++)
                    #pragma unroll
                    for (int nt = 0; nt < 8; nt++)
                        MMA_TF32(acc[mt][nt], Af[mt], Bf[nt]);
            }
            __syncthreads();
            if (tid == 0 && cidx + 2 < 64) {
                mbar_expect(bfu, 32768);
                bulkcp(sbB + st * 32768, (const void*)&g_Bpk[(size_t)(cidx + 2) * 8192], 32768, bfu);
            }
        }

        #pragma unroll
        for (int mt = 0; mt < 4; mt++) {
            #pragma unroll
            for (int rr = 0; rr < 2; rr++) {
                const int t = mt * 2 + rr;
                const float xv = xnv[t];
                #pragma unroll
                for (int nt = 0; nt < 8; nt++) {
                    #pragma unroll
                    for (int j = 0; j < 2; j++) {
                        int code = iter * 256 + nw * 64 + nt * 8 + 2 * tig + j;
                        float dist = fmaf(-2.f, acc[mt][nt][rr * 2 + j], xv) + s_en[code];
                        if (dist < m1[t]) { m2[t] = m1[t]; m1[t] = dist; i1v[t] = code; }
                        else if (dist < m2[t]) m2[t] = dist;
                    }
                }
            }
        }
    }

    #pragma unroll
    for (int t = 0; t < 8; t++) {
        float a = m1[t]; int ai = i1v[t]; float b = m2[t];
        #pragma unroll
        for (int o = 1; o <= 2; o <<= 1) {
            float o1 = __shfl_xor_sync(0xffffffffu, a, o);
            int   oi = __shfl_xor_sync(0xffffffffu, ai, o);
            float o2 = __shfl_xor_sync(0xffffffffu, b, o);
            if (o1 < a || (o1 == a && oi < ai)) { b = fminf(a, o2); a = o1; ai = oi; }
            else b = fminf(b, o1);
        }
        if (tig == 0) {
            int row = mw * 64 + (t >> 1) * 16 + (t & 1) * 8 + g;
            s_mv[nw * 128 + row] = a;
            s_mi[nw * 128 + row] = ai;
            s_m2[nw * 128 + row] = b;
        }
    }
    __syncthreads();

    if (tid < 128) {
        float a = s_mv[tid]; int ai = s_mi[tid]; float b = s_m2[tid];
        #pragma unroll
        for (int w = 1; w < 4; w++) {
            float o1 = s_mv[w * 128 + tid]; int oi = s_mi[w * 128 + tid]; float o2 = s_m2[w * 128 + tid];
            if (o1 < a || (o1 == a && oi < ai)) { b = fminf(a, o2); a = o1; ai = oi; }
            else b = fminf(b, o1);
        }
        int n = n0 + tid;
        if (b - a > TH) {
            g_ind[n] = ai;
            out_ind[n] = (float)ai;
            atomicAdd(&g_counts[ai], 1.0f);
        } else {
            int pos = atomicAdd(&g_nflag, 1);
            g_flag[pos] = n;
            g_best[n] = ~0ull;
        }
    }
}

// ---------------- exact fp32 fallback: 8 pts x half-K per block, smem-staged embed ----------------
__global__ __launch_bounds__(256) void fallback2_kernel(const float* __restrict__ x,
                                                        const float* __restrict__ embed) {
    __shared__ float4 et[256 * 9];   // [code row][8 d-float4 + 1 pad]
    __shared__ float  xs[8 * 256];
    __shared__ int    pts[8];
    __shared__ float  xn[8];
    const int tid  = threadIdx.x;
    const int half = blockIdx.x & 1;
    const int nf   = g_nflag;
    const float4* x4 = (const float4*)x;
    const float4* e4 = (const float4*)embed;

    for (int pg = blockIdx.x >> 1; pg * 8 < nf; pg += gridDim.x >> 1) {
        __syncthreads();
        if (tid < 8) {
            int i = pg * 8 + tid;
            int p = g_flag[i < nf ? i : pg * 8];
            pts[tid] = p;
            xn[tid]  = g_xnorm[p];
        }
        __syncthreads();
        for (int i = tid; i < 512; i += 256)
            ((float4*)xs)[i] = x4[(size_t)pts[i >> 6] * D4 + (i & 63)];

        unsigned long long bp[8];
        #pragma unroll
        for (int p = 0; p < 8; p++) bp[p] = ~0ull;

        for (int chunk = 0; chunk < 4; chunk++) {
            const int cb = half * 1024 + chunk * 256;
            float acc[8];
            #pragma unroll
            for (int p = 0; p < 8; p++) acc[p] = 0.f;
            for (int dc = 0; dc < 8; dc++) {
                __syncthreads();
                #pragma unroll
                for (int r8 = 0; r8 < 8; r8++) {
                    int row = r8 * 32 + (tid >> 3);
                    int c4  = tid & 7;
                    et[row * 9 + c4] = e4[(size_t)(cb + row) * D4 + dc * 8 + c4];
                }
                __syncthreads();
                const float4* xs4 = (const float4*)xs;
                #pragma unroll
                for (int d4 = 0; d4 < 8; d4++) {
                    float4 ev = et[tid * 9 + d4];
                    #pragma unroll
                    for (int p = 0; p < 8; p++) {
                        float4 xv = xs4[p * 64 + dc * 8 + d4];
                        float a = acc[p];
                        a = fmaf(ev.x, xv.x, a);
                        a = fmaf(ev.y, xv.y, a);
                        a = fmaf(ev.z, xv.z, a);
                        a = fmaf(ev.w, xv.w, a);
                        acc[p] = a;
                    }
                }
            }
            int code = cb + tid;
            float en = g_enorm[code];
            #pragma unroll
            for (int p = 0; p < 8; p++) {
                float dist = fmaf(-2.f, acc[p], xn[p]) + en;
                unsigned long long pk =
                    ((unsigned long long)__float_as_uint(dist) << 32) | (unsigned)code;
                if (pk < bp[p]) bp[p] = pk;
            }
        }
        #pragma unroll
        for (int p = 0; p < 8; p++) {
            unsigned long long v = bp[p];
            #pragma unroll
            for (int o = 16; o > 0; o >>= 1) {
                unsigned long long w = __shfl_xor_sync(0xffffffffu, v, o);
                if (w < v) v = w;
            }
            if ((tid & 31) == 0) atomicMin(&g_best[pts[p]], v);
        }
    }
}

__global__ void fb_merge_kernel(float* __restrict__ out_ind) {
    int i = blockIdx.x * blockDim.x + threadIdx.x;
    int nf = g_nflag;
    for (; i < nf; i += gridDim.x * blockDim.x) {
        int n = g_flag[i];
        unsigned long long pk = g_best[n];
        int code = (int)(unsigned)pk;
        g_ind[n] = code;
        out_ind[n] = (float)code;
        atomicAdd(&g_counts[code], 1.0f);
    }
}

// ---------------- quantize gather + per-code feature sums ----------------
__global__ void gather_kernel(const float* __restrict__ x, const float* __restrict__ embed,
                              float* __restrict__ out_q) {
    int t = blockIdx.x * blockDim.x + threadIdx.x;
    int n = t >> 6, q = t & 63;
    int idx = g_ind[n];
    float4 ev = ((const float4*)embed)[(size_t)idx * D4 + q];
    ((float4*)out_q)[(size_t)n * D4 + q] = ev;
    float4 xv = ((const float4*)x)[(size_t)n * D4 + q];
    float* es = g_esum + (size_t)idx * D + q * 4;
    atomicAdd(es + 0, xv.x);
    atomicAdd(es + 1, xv.y);
    atomicAdd(es + 2, xv.z);
    atomicAdd(es + 3, xv.w);
}

// ---------------- new_cluster_size + total ----------------
__global__ void ncs_kernel(const float* __restrict__ cs, float* __restrict__ out_ncs) {
    __shared__ float red[1024];
    int tid = threadIdx.x;
    float s = 0.f;
    for (int k = tid; k < K; k += 1024) {
        float v = cs[k] * 0.99f + 0.01f * g_counts[k];
        out_ncs[k] = v;
        s += v;
    }
    red[tid] = s;
    __syncthreads();
    for (int o = 512; o > 0; o >>= 1) {
        if (tid < o) red[tid] += red[tid + o];
        __syncthreads();
    }
    if (tid == 0) g_total = red[0];
}

// ---------------- new_embed_avg + new_embed ----------------
__global__ void fin_kernel(const float* __restrict__ cs, const float* __restrict__ ea,
                           float* __restrict__ out_nea, float* __restrict__ out_ne) {
    int j = blockIdx.x * blockDim.x + threadIdx.x;
    int k = j >> 8;
    float nea = ea[j] * 0.99f + 0.01f * g_esum[j];
    out_nea[j] = nea;
    float ncs = cs[k] * 0.99f + 0.01f * g_counts[k];
    float tot = g_total;
    float smv = (ncs + 1e-6f) / (tot + 0.002048f) * tot;
    out_ne[j] = nea / smv;
}

// ---------------- launch ----------------
extern "C" void kernel_launch(void* const* d_in, const int* in_sizes, int n_in,
                              void* d_out, int out_size) {
    const float* x  = (const float*)d_in[0];
    const float* em = (const float*)d_in[1];
    const float* cs = (const float*)d_in[2];
    const float* ea = (const float*)d_in[3];
    float* out      = (float*)d_out;

    float* out_q   = out;
    float* out_ind = out + (size_t)N_PTS * D;
    float* out_ncs = out_ind + N_PTS;
    float* out_nea = out_ncs + K;
    float* out_ne  = out_nea + (size_t)K * D;

    void* p_esum; cudaGetSymbolAddress(&p_esum, g_esum);
    void* p_cnt;  cudaGetSymbolAddress(&p_cnt,  g_counts);
    void* p_nfl;  cudaGetSymbolAddress(&p_nfl,  g_nflag);
    cudaMemsetAsync(p_esum, 0, sizeof(float) * K * D, 0);
    cudaMemsetAsync(p_cnt,  0, sizeof(float) * K, 0);
    cudaMemsetAsync(p_nfl,  0, sizeof(int), 0);

    prep_x_kernel<<<N_PTS / 8, 256>>>(x);
    prep_e_kernel<<<K / 8, 256>>>(em);

    cudaFuncSetAttribute(argmin_gemm_kernel, cudaFuncAttributeMaxDynamicSharedMemorySize, 196608);
    argmin_gemm_kernel<<<N_PTS / 128, 256, 196608>>>(out_ind);

    fallback2_kernel<<<4096, 256>>>(x, em);
    fb_merge_kernel<<<64, 256>>>(out_ind);
    gather_kernel<<<(N_PTS * 64) / 256, 256>>>(x, em, out_q);
    ncs_kernel<<<1, 1024>>>(cs, out_ncs);
    fin_kernel<<<(K * D) / 256, 256>>>(cs, ea, out_nea, out_ne);
}